// round 17
// baseline (speedup 1.0000x reference)
#include <cuda_runtime.h>
#include <cuda_bf16.h>
#include <cstdint>
#include <math.h>

#define TOKENS 8192
#define QTOK   2048     // tokens per chain (1 sequence)
#define HDIM   1024
#define NOSC   64
#define TWO_N  128
#define SEQ    2048

// ---------------- scratch (static device memory; no allocations) ----------------
static __device__ __nv_bfloat16 g_xb [TOKENS * HDIM];
static __device__ __nv_bfloat16 g_h  [TOKENS * HDIM];
static __device__ __nv_bfloat16 g_h2 [TOKENS * HDIM];
static __device__ float         g_osc[TOKENS * TWO_N];
static __device__ __nv_bfloat16 g_comb[TOKENS * TWO_N];
static __device__ __nv_bfloat16 g_W1b[HDIM * HDIM];
static __device__ __nv_bfloat16 g_W2b[HDIM * TWO_N];
static __device__ __nv_bfloat16 g_W3b[TWO_N * HDIM];
static __device__ __nv_bfloat16 g_W4b[HDIM * HDIM];
static __device__ float         g_csum[NOSC];

// ---------------- PTX helpers ----------------
__device__ __forceinline__ void cp_async16(void* s, const void* g) {
    uint32_t sa = (uint32_t)__cvta_generic_to_shared(s);
    asm volatile("cp.async.cg.shared.global [%0], [%1], 16;\n" :: "r"(sa), "l"(g));
}
__device__ __forceinline__ void cp_commit() {
    asm volatile("cp.async.commit_group;\n" ::: "memory");
}
template <int N>
__device__ __forceinline__ void cp_wait() {
    asm volatile("cp.async.wait_group %0;\n" :: "n"(N) : "memory");
}
__device__ __forceinline__ void ldmatrix_x4(uint32_t* r, const void* p) {
    uint32_t a = (uint32_t)__cvta_generic_to_shared(p);
    asm volatile("ldmatrix.sync.aligned.m8n8.x4.shared.b16 {%0,%1,%2,%3}, [%4];\n"
        : "=r"(r[0]), "=r"(r[1]), "=r"(r[2]), "=r"(r[3]) : "r"(a));
}
__device__ __forceinline__ void ldmatrix_x4_trans(uint32_t* r, const void* p) {
    uint32_t a = (uint32_t)__cvta_generic_to_shared(p);
    asm volatile("ldmatrix.sync.aligned.m8n8.x4.trans.shared.b16 {%0,%1,%2,%3}, [%4];\n"
        : "=r"(r[0]), "=r"(r[1]), "=r"(r[2]), "=r"(r[3]) : "r"(a));
}
// NON-volatile: ptxas schedules by register dependencies.
__device__ __forceinline__ void mma16816(float* d, const uint32_t* a, uint32_t b0, uint32_t b1) {
    asm("mma.sync.aligned.m16n8k16.row.col.f32.bf16.bf16.f32 "
        "{%0,%1,%2,%3}, {%4,%5,%6,%7}, {%8,%9}, {%0,%1,%2,%3};\n"
        : "+f"(d[0]), "+f"(d[1]), "+f"(d[2]), "+f"(d[3])
        : "r"(a[0]), "r"(a[1]), "r"(a[2]), "r"(a[3]), "r"(b0), "r"(b1));
}

// ---------------- prep A: weight converts + coupling csum (shared by all chains) ----------------
// grid = 2304 (weights) + 1 (csum) = 2305 blocks of 256 threads
__global__ void k_prep_w(const float* __restrict__ W1, const float* __restrict__ W2,
                         const float* __restrict__ W3, const float* __restrict__ W4,
                         const float* __restrict__ coupling) {
    const int b = blockIdx.x;
    if (b < 2304) {
        const float* in; __nv_bfloat16* out; int base;
        if (b < 1024)      { in = W1; out = g_W1b; base = b * 1024; }
        else if (b < 1152) { in = W2; out = g_W2b; base = (b - 1024) * 1024; }
        else if (b < 1280) { in = W3; out = g_W3b; base = (b - 1152) * 1024; }
        else               { in = W4; out = g_W4b; base = (b - 1280) * 1024; }
        int i = base + threadIdx.x * 4;
        float4 v = *reinterpret_cast<const float4*>(in + i);
        *reinterpret_cast<__nv_bfloat162*>(out + i)     = __floats2bfloat162_rn(v.x, v.y);
        *reinterpret_cast<__nv_bfloat162*>(out + i + 2) = __floats2bfloat162_rn(v.z, v.w);
    } else {
        int m = threadIdx.x;
        if (m < NOSC) {
            float s = 0.f;
            #pragma unroll
            for (int j = 0; j < NOSC; j++) s += coupling[m * NOSC + j];
            g_csum[m] = s;
        }
    }
}

// ---------------- prep B: per-chain x-slice convert (2048 blocks per chain) ----------------
__global__ void k_prep_x(const float* __restrict__ x, int tokBase) {
    int i = ((size_t)tokBase * HDIM) + blockIdx.x * 1024 + threadIdx.x * 4;
    float4 v = *reinterpret_cast<const float4*>(x + i);
    *reinterpret_cast<__nv_bfloat162*>(g_xb + i)     = __floats2bfloat162_rn(v.x, v.y);
    *reinterpret_cast<__nv_bfloat162*>(g_xb + i + 2) = __floats2bfloat162_rn(v.z, v.w);
}

// ---------------- oscillator dynamics: 1 warp per token, 2 osc per lane ----------------
__global__ void k_dynamics(const float* __restrict__ t, const float* __restrict__ Wt,
                           const float* __restrict__ bt, const float* __restrict__ freq,
                           const float* __restrict__ mu_p, int tokBase) {
    const int tok  = tokBase + blockIdx.x * 8 + (threadIdx.x >> 5);
    const int lane = threadIdx.x & 31;
    const int i0 = lane, i1 = lane + 32;
    __nv_bfloat16* out = g_comb + (size_t)tok * TWO_N;

    if ((tok & (SEQ - 1)) == 0) {
        const float* cur = g_osc + (size_t)tok * TWO_N;
        out[i0]        = __float2bfloat16(cur[i0]);
        out[i1]        = __float2bfloat16(cur[i1]);
        out[NOSC + i0] = __float2bfloat16(cur[NOSC + i0]);
        out[NOSC + i1] = __float2bfloat16(cur[NOSC + i1]);
        return;
    }

    const float* prev = g_osc + (size_t)(tok - 1) * TWO_N;
    float p0 = prev[i0], p1 = prev[i1];
    float a0 = prev[NOSC + i0], a1 = prev[NOSC + i1];
    float sp0, cp0, sp1, cp1;
    sincosf(p0, &sp0, &cp0);
    sincosf(p1, &sp1, &cp1);

    float cs0 = g_csum[i0], cs1 = g_csum[i1];
    float vc = cs0 * cp0 + cs1 * cp1;
    float vs = cs0 * sp0 + cs1 * sp1;
    #pragma unroll
    for (int o = 16; o > 0; o >>= 1) {
        vc += __shfl_xor_sync(0xffffffffu, vc, o);
        vs += __shfl_xor_sync(0xffffffffu, vs, o);
    }

    const float tv = t[tok];
    const float mu = *mu_p;

    float cpl0 = sp0 * vc - cp0 * vs;
    float cpl1 = sp1 * vc - cp1 * vs;
    float d0 = freq[i0] + cpl0 * 0.1f + (tv * Wt[i0] + bt[i0]) * 0.1f;
    float d1 = freq[i1] + cpl1 * 0.1f + (tv * Wt[i1] + bt[i1]) * 0.1f;
    float pn0 = p0 + d0 * 0.1f;
    float pn1 = p1 + d1 * 0.1f;

    float da0 = (mu - 0.1f) * a0 - a0 * a0 * a0;
    float da1 = (mu - 0.1f) * a1 - a1 * a1 * a1;
    float an0 = tanhf(a0 + da0 * 0.1f);
    float an1 = tanhf(a1 + da1 * 0.1f);

    out[i0]        = __float2bfloat16(pn0);
    out[i1]        = __float2bfloat16(pn1);
    out[NOSC + i0] = __float2bfloat16(an0);
    out[NOSC + i1] = __float2bfloat16(an1);
}

// ---------------- tiled bf16 mma.sync GEMM, epoch pipeline + fine-grained interleave ----------------
// 128-thread CTAs, warp grid 2x2, warp tile (BM/2) x (BN/2).
// 4 slots of BK=32 as two pairs; one cp.async.wait+__syncthreads per 64 K.
// EPI: 0 = bias+leaky_relu -> bf16 ; 1 = bias -> f32 ; 2 = resid + 0.1*(acc+bias) -> f32
#define BK 32
#define ASTR 40     // A smem row stride (elems): 80B ≡ 16 mod 128
#define NTHR 128

template <int BM, int BN, int EPI>
__global__ void __launch_bounds__(NTHR, 2)
k_gemm(const __nv_bfloat16* __restrict__ A, const __nv_bfloat16* __restrict__ B,
       const float* __restrict__ bias, void* __restrict__ outp,
       const float* __restrict__ resid, int M, int N, int K) {
    constexpr int BSTR = BN + 8;
    constexpr int WMT = BM / 2;
    constexpr int WNT = BN / 2;
    constexpr int NM = WMT / 16;
    constexpr int NN = WNT / 8;
    constexpr int NB = WNT / 16;
    constexpr int AST = BM * ASTR;
    constexpr int BST = BK * BSTR;
    constexpr int NGAP = NM + NB;              // ldmatrix ops per kk-step
    constexpr int NMMA = NM * NN;              // MMAs per kk-step
    constexpr int NAPC = BM * 4 / NTHR;        // A cp.async pieces per thread
    constexpr int NBPC = BK * (BN / 8) / NTHR; // B cp.async pieces per thread
    static_assert(NAPC + NBPC == NGAP, "cp pieces must equal ldmatrix gaps");

    extern __shared__ __align__(16) char smem[];
    __nv_bfloat16* As = reinterpret_cast<__nv_bfloat16*>(smem);   // [4][BM][ASTR]
    __nv_bfloat16* Bs = As + 4 * AST;                             // [4][BK][BSTR]

    const int tid  = threadIdx.x;
    const int lane = tid & 31;
    const int warp = tid >> 5;
    const int wm = warp >> 1;
    const int wn = warp & 1;
    const int bm0 = blockIdx.y * BM;
    const int bn0 = blockIdx.x * BN;
    const int KT = K / BK;
    const int NE = KT / 2;

    float acc[NM][NN][4];
    #pragma unroll
    for (int a = 0; a < NM; a++)
        #pragma unroll
        for (int b = 0; b < NN; b++)
            #pragma unroll
            for (int c = 0; c < 4; c++) acc[a][b][c] = 0.f;

    uint32_t afr[2][NM][4];
    uint32_t bfr[2][NB][4];

    auto mma_one = [&](int buf, int m) {
        int im = m / NN, in = m % NN;
        mma16816(acc[im][in], afr[buf][im],
                 bfr[buf][in >> 1][(in & 1) * 2], bfr[buf][in >> 1][(in & 1) * 2 + 1]);
    };
    auto ld_gap = [&](int buf, int s, int kk, int g) {
        if (g < NM)
            ldmatrix_x4(afr[buf][g],
                As + s * AST + (wm * WMT + g * 16 + (lane & 15)) * ASTR + kk * 16 + (lane >> 4) * 8);
        else
            ldmatrix_x4_trans(bfr[buf][g - NM],
                Bs + s * BST + (kk * 16 + (lane & 15)) * BSTR + wn * WNT + (g - NM) * 16 + (lane >> 4) * 8);
    };
    auto cp_piece = [&](int kt, int s, int i) {
        if (i < NAPC) {
            int idx = tid + i * NTHR;
            int r = idx >> 2, c = idx & 3;
            cp_async16(As + s * AST + r * ASTR + c * 8, A + (size_t)(bm0 + r) * K + kt * BK + c * 8);
        } else {
            int idx = tid + (i - NAPC) * NTHR;
            int r = idx / (BN / 8), c = idx % (BN / 8);
            cp_async16(Bs + s * BST + r * BSTR + c * 8, B + (size_t)(kt * BK + r) * N + bn0 + c * 8);
        }
    };
    auto load_burst = [&](int kt, int s) {
        #pragma unroll
        for (int i = 0; i < NGAP; i++) cp_piece(kt, s, i);
        cp_commit();
    };
    auto step = [&](int cbuf, int lbuf, int ls, int lkk, int ldkt, int lds, bool docp) {
        #pragma unroll
        for (int g = 0; g < NGAP; g++) {
            const int m0 = (g * NMMA) / NGAP, m1 = ((g + 1) * NMMA) / NGAP;
            #pragma unroll
            for (int m = m0; m < m1; m++) mma_one(cbuf, m);
            ld_gap(lbuf, ls, lkk, g);
            if (docp) cp_piece(ldkt, lds, g);
        }
        if (docp) cp_commit();
    };

    // prologue
    load_burst(0, 0);
    load_burst(1, 1);
    cp_wait<0>();
    __syncthreads();
    #pragma unroll
    for (int g = 0; g < NGAP; g++) ld_gap(0, 0, 0, g);

    for (int e = 0; e < NE; e++) {
        const int p  = e & 1;
        const int s0 = 2 * p, s1 = s0 + 1;
        const int q0 = 2 - 2 * p, q1 = q0 + 1;
        const int ktn = 2 * (e + 1);
        const bool more = (ktn < KT);

        step(0, 1, s0, 1, ktn,     q0, more);
        step(1, 0, s1, 0, ktn + 1, q1, more);
        step(0, 1, s1, 1, 0, 0, false);

        constexpr int HALF = NMMA / 2;
        #pragma unroll
        for (int m = 0; m < HALF; m++) mma_one(1, m);
        if (e + 1 < NE) {
            cp_wait<0>();
            __syncthreads();
        }
        #pragma unroll
        for (int g = 0; g < NGAP; g++) {
            const int m0 = HALF + (g * (NMMA - HALF)) / NGAP;
            const int m1 = HALF + ((g + 1) * (NMMA - HALF)) / NGAP;
            #pragma unroll
            for (int m = m0; m < m1; m++) mma_one(1, m);
            if (e + 1 < NE) ld_gap(0, q0, 0, g);
        }
    }

    // epilogue straight from registers
    #pragma unroll
    for (int im = 0; im < NM; im++) {
        const int r0 = bm0 + wm * WMT + im * 16 + (lane >> 2);
        #pragma unroll
        for (int in = 0; in < NN; in++) {
            const int c0 = bn0 + wn * WNT + in * 8 + (lane & 3) * 2;
            const float bv0 = bias[c0], bv1 = bias[c0 + 1];
            #pragma unroll
            for (int half = 0; half < 2; half++) {
                const int r = r0 + half * 8;
                float v0 = acc[im][in][half * 2 + 0] + bv0;
                float v1 = acc[im][in][half * 2 + 1] + bv1;
                if (EPI == 0) {
                    v0 = v0 >= 0.f ? v0 : 0.2f * v0;
                    v1 = v1 >= 0.f ? v1 : 0.2f * v1;
                    *reinterpret_cast<__nv_bfloat162*>(
                        (__nv_bfloat16*)outp + (size_t)r * N + c0) = __floats2bfloat162_rn(v0, v1);
                } else if (EPI == 1) {
                    float2 o; o.x = v0; o.y = v1;
                    *reinterpret_cast<float2*>((float*)outp + (size_t)r * N + c0) = o;
                } else {
                    float2 xv = *reinterpret_cast<const float2*>(resid + (size_t)r * N + c0);
                    float2 o; o.x = xv.x + 0.1f * v0; o.y = xv.y + 0.1f * v1;
                    *reinterpret_cast<float2*>((float*)outp + (size_t)r * N + c0) = o;
                }
            }
        }
    }
}

// ---------------- launch: four captured streams; per-chain x-convert + chain ----------------
extern "C" void kernel_launch(void* const* d_in, const int* in_sizes, int n_in,
                              void* d_out, int out_size) {
    const float* x        = (const float*)d_in[0];
    const float* t        = (const float*)d_in[1];
    const float* W1       = (const float*)d_in[2];
    const float* b1       = (const float*)d_in[3];
    const float* W2       = (const float*)d_in[4];
    const float* b2       = (const float*)d_in[5];
    const float* W3       = (const float*)d_in[6];
    const float* b3       = (const float*)d_in[7];
    const float* W4       = (const float*)d_in[8];
    const float* b4       = (const float*)d_in[9];
    const float* Wt       = (const float*)d_in[10];
    const float* bt       = (const float*)d_in[11];
    const float* coupling = (const float*)d_in[12];
    const float* freq     = (const float*)d_in[13];
    const float* mu       = (const float*)d_in[14];
    float* out = (float*)d_out;

    void *p_xb, *p_h, *p_h2, *p_osc, *p_comb, *p_W1, *p_W2, *p_W3, *p_W4;
    cudaGetSymbolAddress(&p_xb,   g_xb);
    cudaGetSymbolAddress(&p_h,    g_h);
    cudaGetSymbolAddress(&p_h2,   g_h2);
    cudaGetSymbolAddress(&p_osc,  g_osc);
    cudaGetSymbolAddress(&p_comb, g_comb);
    cudaGetSymbolAddress(&p_W1,   g_W1b);
    cudaGetSymbolAddress(&p_W2,   g_W2b);
    cudaGetSymbolAddress(&p_W3,   g_W3b);
    cudaGetSymbolAddress(&p_W4,   g_W4b);

    // lazily-created side streams + events (host resources, created once)
    static cudaStream_t s[3] = {nullptr, nullptr, nullptr};
    static cudaEvent_t evFork = nullptr;
    static cudaEvent_t evJoin[3] = {nullptr, nullptr, nullptr};
    if (!s[0]) {
        for (int i = 0; i < 3; i++) {
            cudaStreamCreateWithFlags(&s[i], cudaStreamNonBlocking);
            cudaEventCreateWithFlags(&evJoin[i], cudaEventDisableTiming);
        }
        cudaEventCreateWithFlags(&evFork, cudaEventDisableTiming);
    }

    // smem sizes (bytes)
    const int SM_128 = 4 * (128 * ASTR + BK * (128 + 8)) * 2;  // 75776
    const int SM_SML = 4 * (32  * ASTR + BK * (128 + 8)) * 2;  // 45056
    cudaFuncSetAttribute(k_gemm<128, 128, 0>, cudaFuncAttributeMaxDynamicSharedMemorySize, SM_128);
    cudaFuncSetAttribute(k_gemm<128, 128, 2>, cudaFuncAttributeMaxDynamicSharedMemorySize, SM_128);
    cudaFuncSetAttribute(k_gemm<32, 128, 1>,  cudaFuncAttributeMaxDynamicSharedMemorySize, SM_SML);

    // shared prep (weights + csum) on the origin stream, then fork
    k_prep_w<<<2305, 256>>>(W1, W2, W3, W4, coupling);
    cudaEventRecord(evFork, 0);
    for (int i = 0; i < 3; i++) cudaStreamWaitEvent(s[i], evFork, 0);

    dim3 gBig(HDIM / 128, QTOK / 128);   // (8, 16) per chain
    dim3 gOsc(1, QTOK / 32);             // (1, 64) per chain

    // per-chain pipeline on stream `st`, token offset `off` (incl. its x-slice convert)
    auto chain = [&](cudaStream_t st, int off) {
        const __nv_bfloat16* xb  = (const __nv_bfloat16*)p_xb + (size_t)off * HDIM;
        __nv_bfloat16* h   = (__nv_bfloat16*)p_h   + (size_t)off * HDIM;
        __nv_bfloat16* h2  = (__nv_bfloat16*)p_h2  + (size_t)off * HDIM;
        float*         osc = (float*)p_osc         + (size_t)off * TWO_N;
        __nv_bfloat16* cmb = (__nv_bfloat16*)p_comb + (size_t)off * TWO_N;

        // convert this chain's x slice
        k_prep_x<<<QTOK, 256, 0, st>>>(x, off);
        // h = lrelu(x @ W1 + b1)
        k_gemm<128, 128, 0><<<gBig, NTHR, SM_128, st>>>(xb, (const __nv_bfloat16*)p_W1,
                                                        b1, h, nullptr, QTOK, HDIM, HDIM);
        // osc = h @ W2 + b2 (f32)
        k_gemm<32, 128, 1><<<gOsc, NTHR, SM_SML, st>>>(h, (const __nv_bfloat16*)p_W2,
                                                       b2, osc, nullptr, QTOK, TWO_N, HDIM);
        // oscillator dynamics -> combined (bf16)
        k_dynamics<<<QTOK / 8, 256, 0, st>>>(t, Wt, bt, freq, mu, off);
        // h2 = lrelu(combined @ W3 + b3)
        k_gemm<128, 128, 0><<<gBig, NTHR, SM_128, st>>>(cmb, (const __nv_bfloat16*)p_W3,
                                                        b3, h2, nullptr, QTOK, HDIM, TWO_N);
        // out = x + 0.1*(h2 @ W4 + b4)
        k_gemm<128, 128, 2><<<gBig, NTHR, SM_128, st>>>(h2, (const __nv_bfloat16*)p_W4,
                                                        b4, out + (size_t)off * HDIM,
                                                        x + (size_t)off * HDIM, QTOK, HDIM, HDIM);
    };

    chain((cudaStream_t)0, 0);           // sequence 0 on the origin stream
    chain(s[0], QTOK);                   // sequence 1
    chain(s[1], 2 * QTOK);               // sequence 2
    chain(s[2], 3 * QTOK);               // sequence 3

    // join: origin stream waits for all side chains
    for (int i = 0; i < 3; i++) {
        cudaEventRecord(evJoin[i], s[i]);
        cudaStreamWaitEvent((cudaStream_t)0, evJoin[i], 0);
    }
}